// round 16
// baseline (speedup 1.0000x reference)
#include <cuda_runtime.h>
#include <cstdint>

#define T_TOK 8192
#define MDIM  1024
#define NEXP  8
#define DFFD  4096
#define CAP   1280

// ---------------- device scratch ----------------
__device__ __align__(256) float g_disp[(size_t)NEXP * CAP * MDIM];
__device__ __align__(256) float g_h   [(size_t)NEXP * CAP * DFFD];
__device__ __align__(256) float g_oute[(size_t)NEXP * CAP * MDIM];
__device__ int   g_expert[T_TOK];
__device__ float g_gate[T_TOK];
__device__ int   g_slot[T_TOK];

// ---------------- helpers ----------------
__device__ __forceinline__ uint32_t smem_u32(const void* p) {
    uint32_t a;
    asm("{ .reg .u64 t; cvta.to.shared.u64 t, %1; cvt.u32.u64 %0, t; }" : "=r"(a) : "l"(p));
    return a;
}
__device__ __forceinline__ float tf32r(float v) {
    uint32_t u;
    asm("cvt.rna.tf32.f32 %0, %1;" : "=r"(u) : "f"(v));
    return __uint_as_float(u);
}

#define CPASYNC16(dst, src) \
    asm volatile("cp.async.cg.shared.global [%0], [%1], 16;" :: "r"(dst), "l"(src) : "memory")
#define CPCOMMIT()  asm volatile("cp.async.commit_group;" ::: "memory")
#define CPWAIT(n)   asm volatile("cp.async.wait_group %0;" :: "n"(n) : "memory")

__device__ __forceinline__ void mma_tf32(float* d, const uint32_t* a, uint32_t b0, uint32_t b1) {
    asm volatile(
        "mma.sync.aligned.m16n8k8.row.col.f32.tf32.tf32.f32 "
        "{%0,%1,%2,%3}, {%4,%5,%6,%7}, {%8,%9}, {%0,%1,%2,%3};"
        : "+f"(d[0]), "+f"(d[1]), "+f"(d[2]), "+f"(d[3])
        : "r"(a[0]), "r"(a[1]), "r"(a[2]), "r"(a[3]), "r"(b0), "r"(b1));
}

__device__ __forceinline__ void ldsm_x4(uint32_t* r, uint32_t addr) {
    asm volatile("ldmatrix.sync.aligned.m8n8.x4.shared.b16 {%0,%1,%2,%3}, [%4];"
        : "=r"(r[0]), "=r"(r[1]), "=r"(r[2]), "=r"(r[3]) : "r"(addr));
}

// ---------------- K1: gating ----------------
__global__ void gate_kernel(const float* __restrict__ x, const float* __restrict__ wg)
{
    int warp = (blockIdx.x * blockDim.x + threadIdx.x) >> 5;
    int lane = threadIdx.x & 31;
    if (warp >= T_TOK) return;

    const float* xr = x + (size_t)warp * MDIM;
    float acc[8] = {0.f,0.f,0.f,0.f,0.f,0.f,0.f,0.f};

    #pragma unroll 4
    for (int i = 0; i < MDIM / 32; i++) {
        int m = i * 32 + lane;
        float xv = __ldg(xr + m);
        const float4* w4 = reinterpret_cast<const float4*>(wg + (size_t)m * NEXP);
        float4 a = w4[0], b = w4[1];
        acc[0] += xv * a.x; acc[1] += xv * a.y;
        acc[2] += xv * a.z; acc[3] += xv * a.w;
        acc[4] += xv * b.x; acc[5] += xv * b.y;
        acc[6] += xv * b.z; acc[7] += xv * b.w;
    }
    #pragma unroll
    for (int e = 0; e < 8; e++)
        #pragma unroll
        for (int off = 16; off > 0; off >>= 1)
            acc[e] += __shfl_xor_sync(0xffffffffu, acc[e], off);

    if (lane == 0) {
        float mx = acc[0]; int bi = 0;
        #pragma unroll
        for (int e = 1; e < 8; e++)
            if (acc[e] > mx) { mx = acc[e]; bi = e; }
        float s = 0.f;
        #pragma unroll
        for (int e = 0; e < 8; e++) s += expf(acc[e] - mx);
        g_expert[warp] = bi;
        g_gate[warp]   = 1.0f / s;
    }
}

// ---------------- K2: ordered per-expert rank (two-level shuffle scan) ----------------
__global__ void pos_kernel()
{
    __shared__ int wtot[32][8];
    const int tid = threadIdx.x;
    const int lane = tid & 31, wp = tid >> 5;
    const int base_t = tid * 8;

    int cnt[8] = {0,0,0,0,0,0,0,0};
    int loc[8];
    #pragma unroll
    for (int i = 0; i < 8; i++) {
        int e = g_expert[base_t + i];
        loc[i] = e;
        cnt[e]++;
    }

    int inc[8];
    #pragma unroll
    for (int e = 0; e < 8; e++) inc[e] = cnt[e];
    #pragma unroll
    for (int off = 1; off < 32; off <<= 1) {
        #pragma unroll
        for (int e = 0; e < 8; e++) {
            int v = __shfl_up_sync(0xffffffffu, inc[e], off);
            if (lane >= off) inc[e] += v;
        }
    }
    if (lane == 31) {
        #pragma unroll
        for (int e = 0; e < 8; e++) wtot[wp][e] = inc[e];
    }
    __syncthreads();

    if (wp == 0) {
        int t[8];
        #pragma unroll
        for (int e = 0; e < 8; e++) t[e] = wtot[lane][e];
        #pragma unroll
        for (int off = 1; off < 32; off <<= 1) {
            #pragma unroll
            for (int e = 0; e < 8; e++) {
                int v = __shfl_up_sync(0xffffffffu, t[e], off);
                if (lane >= off) t[e] += v;
            }
        }
        #pragma unroll
        for (int e = 0; e < 8; e++) wtot[lane][e] = t[e];
    }
    __syncthreads();

    int run[8];
    #pragma unroll
    for (int e = 0; e < 8; e++)
        run[e] = (wp > 0 ? wtot[wp - 1][e] : 0) + inc[e] - cnt[e];

    #pragma unroll
    for (int i = 0; i < 8; i++) {
        int e = loc[i];
        int p = run[e]++;
        g_slot[base_t + i] = (p < CAP) ? (e * CAP + p) : -1;
    }
}

// ---------------- K3: scatter (+ tf32 rounding) ----------------
__global__ void scatter_kernel(const float* __restrict__ x)
{
    int t = blockIdx.x;
    int s = g_slot[t];
    if (s < 0) return;
    float4 v = reinterpret_cast<const float4*>(x + (size_t)t * MDIM)[threadIdx.x];
    v.x = tf32r(v.x); v.y = tf32r(v.y); v.z = tf32r(v.z); v.w = tf32r(v.w);
    reinterpret_cast<float4*>(g_disp + (size_t)s * MDIM)[threadIdx.x] = v;
}

// ---------------- K4: tf32 mma.sync GEMM ----------------
// 512 threads, 16 warps (4x4), warp tile 32x32, CTA tile 128x128, BK=32.
// 3-stage cp.async, one syncthreads/iter. A via ldmatrix.x4.
// B via LDS.128 with the n-permuted MMA mapping:
//   MMA instance j covers global columns { wn + b*4 + j : b=0..7 }.
//   -> lane (g,tg) B operands for j=0..3 = uint4 at bs[(k+tg)][wn+4g] (+4 k rows).
//   Bank check (stride 136, 8-lane phases): banks 8tg+4g+{0..3} -> all 32. OK.
// smem As [128][36], Bs [32][136].
#define A_ST 4608   // 128*36 floats per stage
#define B_ST 4352   // 32*136 floats per stage
#define NSTAGE 3
#define GEMM_SMEM (NSTAGE * (A_ST + B_ST) * 4)   // 107520 bytes

template<bool RELU, bool CVT>
__global__ void __launch_bounds__(512, 2)
moe_gemm(const float* __restrict__ Ag, const float* __restrict__ Bg,
         const float* __restrict__ biasg, float* __restrict__ Cg,
         int Ndim, int Kdim)
{
    extern __shared__ float sm[];
    const uint32_t su = smem_u32(sm);
    const int tid = threadIdx.x;
    const int wid = tid >> 5, lane = tid & 31;
    const int g = lane >> 2, tg = lane & 3;
    const int wm = (wid >> 2) * 32;          // warp row base: 0/32/64/96
    const int wn = (wid & 3) * 32;           // warp col base: 0/32/64/96

    // ldmatrix per-lane source row/col within the A tile
    const int lrow = (lane & 7) + ((lane >> 3) & 1) * 8;   // 0..15
    const int lcol = (lane >> 4) * 4;                      // 0 or 4

    const int z = blockIdx.z;
    const float* A = Ag + (size_t)z * CAP * Kdim + (size_t)(blockIdx.y * 128) * Kdim;
    const float* B = Bg + (size_t)z * Kdim * Ndim + blockIdx.x * 128;
    const float* bias = biasg + (size_t)z * Ndim + blockIdx.x * 128;
    float* C = Cg + (size_t)z * CAP * Ndim + (size_t)(blockIdx.y * 128) * Ndim + blockIdx.x * 128;

    // loader assignments (512 threads)
    const int arow = tid >> 2, acol = (tid & 3) * 8;    // A: 4 thr/row, 2x16B each
    const int brow = tid >> 4, bcol = (tid & 15) * 4;   // B: 16 thr/row, 2x16B (cols bcol, bcol+64)

    float acc[2][4][4];
    #pragma unroll
    for (int i = 0; i < 2; i++)
        #pragma unroll
        for (int j = 0; j < 4; j++)
            #pragma unroll
            for (int q = 0; q < 4; q++) acc[i][j][q] = 0.f;

    auto load_stage = [&](int kt, int s) {
        const float* ag = A + (size_t)arow * Kdim + kt * 32 + acol;
        uint32_t ad = su + (uint32_t)(s * (A_ST + B_ST) + arow * 36 + acol) * 4;
        CPASYNC16(ad,      ag);
        CPASYNC16(ad + 16, ag + 4);
        const float* bg = B + (size_t)(kt * 32 + brow) * Ndim + bcol;
        uint32_t bd = su + (uint32_t)(s * (A_ST + B_ST) + A_ST + brow * 136 + bcol) * 4;
        CPASYNC16(bd,       bg);
        CPASYNC16(bd + 256, bg + 64);   // +64 cols = +256 bytes
        CPCOMMIT();
    };

    const int KT = Kdim >> 5;   // 32 or 128
    load_stage(0, 0);
    load_stage(1, 1);

    int s = 0;          // stage holding kt
    int sw = 2;         // stage to write kt+2 into
    for (int kt = 0; kt < KT; kt++) {
        if (kt + 1 < KT) { CPWAIT(1); } else { CPWAIT(0); }
        __syncthreads();

        const uint32_t asu = su + (uint32_t)(s * (A_ST + B_ST)) * 4;
        const float* bs = sm + s * (A_ST + B_ST) + A_ST;
        const uint32_t abase = asu + (uint32_t)((wm + lrow) * 36 + lcol) * 4;
        const uint4* bbase = reinterpret_cast<const uint4*>(bs + wn + 4 * g);

        #pragma unroll
        for (int ks = 0; ks < 4; ks++) {
            const int k0 = ks * 8;
            uint32_t afr[2][4];
            ldsm_x4(afr[0], abase + (uint32_t)(k0) * 4);
            ldsm_x4(afr[1], abase + (uint32_t)(16 * 36 + k0) * 4);
            // uint4 rows: (k0+tg)*136/4 = (k0+tg)*34 uint4s
            uint4 q0 = bbase[(size_t)(k0 + tg) * 34];
            uint4 q1 = bbase[(size_t)(k0 + tg + 4) * 34];
            mma_tf32(acc[0][0], afr[0], q0.x, q1.x);
            mma_tf32(acc[1][0], afr[1], q0.x, q1.x);
            mma_tf32(acc[0][1], afr[0], q0.y, q1.y);
            mma_tf32(acc[1][1], afr[1], q0.y, q1.y);
            mma_tf32(acc[0][2], afr[0], q0.z, q1.z);
            mma_tf32(acc[1][2], afr[1], q0.z, q1.z);
            mma_tf32(acc[0][3], afr[0], q0.w, q1.w);
            mma_tf32(acc[1][3], afr[1], q0.w, q1.w);
        }

        if (kt + 2 < KT) load_stage(kt + 2, sw);
        if (++s == NSTAGE) s = 0;
        if (++sw == NSTAGE) sw = 0;
    }

    // epilogue (n-permuted mapping: c[0] col = wn+8tg+j, c[1] col = wn+8tg+4+j)
    const float4 bv0 = *reinterpret_cast<const float4*>(bias + wn + 8 * tg);
    const float4 bv1 = *reinterpret_cast<const float4*>(bias + wn + 8 * tg + 4);
    const float bb0[4] = { bv0.x, bv0.y, bv0.z, bv0.w };
    const float bb1[4] = { bv1.x, bv1.y, bv1.z, bv1.w };

    #pragma unroll
    for (int i = 0; i < 2; i++) {
        const int r0 = wm + i * 16 + g;
        float o00[4], o01[4], o10[4], o11[4];
        #pragma unroll
        for (int j = 0; j < 4; j++) {
            float v00 = acc[i][j][0] + bb0[j];
            float v01 = acc[i][j][1] + bb1[j];
            float v10 = acc[i][j][2] + bb0[j];
            float v11 = acc[i][j][3] + bb1[j];
            if (RELU) {
                v00 = fmaxf(v00, 0.f); v01 = fmaxf(v01, 0.f);
                v10 = fmaxf(v10, 0.f); v11 = fmaxf(v11, 0.f);
            }
            if (CVT) {
                v00 = tf32r(v00); v01 = tf32r(v01);
                v10 = tf32r(v10); v11 = tf32r(v11);
            }
            o00[j] = v00; o01[j] = v01; o10[j] = v10; o11[j] = v11;
        }
        float* c0 = C + (size_t)r0 * Ndim + wn + 8 * tg;
        float* c1 = C + (size_t)(r0 + 8) * Ndim + wn + 8 * tg;
        *reinterpret_cast<float4*>(c0)     = *reinterpret_cast<float4*>(o00);
        *reinterpret_cast<float4*>(c0 + 4) = *reinterpret_cast<float4*>(o01);
        *reinterpret_cast<float4*>(c1)     = *reinterpret_cast<float4*>(o10);
        *reinterpret_cast<float4*>(c1 + 4) = *reinterpret_cast<float4*>(o11);
    }
}

// ---------------- K6: gather ----------------
__global__ void gather_kernel(float* __restrict__ out)
{
    int t = blockIdx.x;
    int s = g_slot[t];
    float4* dst = reinterpret_cast<float4*>(out + (size_t)t * MDIM);
    if (s < 0) {
        dst[threadIdx.x] = make_float4(0.f, 0.f, 0.f, 0.f);
        return;
    }
    float g = g_gate[t];
    float4 v = reinterpret_cast<const float4*>(g_oute + (size_t)s * MDIM)[threadIdx.x];
    dst[threadIdx.x] = make_float4(v.x * g, v.y * g, v.z * g, v.w * g);
}

// ---------------- launch ----------------
extern "C" void kernel_launch(void* const* d_in, const int* in_sizes, int n_in,
                              void* d_out, int out_size)
{
    const float* x  = (const float*)d_in[0];
    const float* wg = (const float*)d_in[1];
    const float* w1 = (const float*)d_in[2];
    const float* b1 = (const float*)d_in[3];
    const float* w2 = (const float*)d_in[4];
    const float* b2 = (const float*)d_in[5];
    float* out = (float*)d_out;

    float *disp, *h, *oute;
    cudaGetSymbolAddress((void**)&disp, g_disp);
    cudaGetSymbolAddress((void**)&h,    g_h);
    cudaGetSymbolAddress((void**)&oute, g_oute);

    cudaFuncSetAttribute(moe_gemm<true, true>,
                         cudaFuncAttributeMaxDynamicSharedMemorySize, GEMM_SMEM);
    cudaFuncSetAttribute(moe_gemm<false, false>,
                         cudaFuncAttributeMaxDynamicSharedMemorySize, GEMM_SMEM);

    gate_kernel<<<T_TOK / 8, 256>>>(x, wg);
    pos_kernel<<<1, 1024>>>();
    scatter_kernel<<<T_TOK, 256>>>(x);

    moe_gemm<true, true><<<dim3(DFFD / 128, CAP / 128, NEXP), 512, GEMM_SMEM>>>(
        disp, w1, b1, h, DFFD, MDIM);

    moe_gemm<false, false><<<dim3(MDIM / 128, CAP / 128, NEXP), 512, GEMM_SMEM>>>(
        h, w2, b2, oute, MDIM, DFFD);

    gather_kernel<<<T_TOK, 256>>>(out);
}

// round 17
// speedup vs baseline: 1.1648x; 1.1648x over previous
#include <cuda_runtime.h>
#include <cstdint>

#define T_TOK 8192
#define MDIM  1024
#define NEXP  8
#define DFFD  4096
#define CAP   1280

// ---------------- device scratch ----------------
__device__ __align__(256) float g_disp [(size_t)NEXP * CAP * MDIM];
__device__ __align__(256) float g_h    [(size_t)NEXP * CAP * DFFD];
__device__ __align__(256) float g_oute [(size_t)NEXP * CAP * MDIM];
__device__ __align__(256) float g_oute2[(size_t)NEXP * CAP * MDIM];
__device__ float g_zbias[MDIM];           // zero-initialized, never written
__device__ int   g_expert[T_TOK];
__device__ float g_gate[T_TOK];
__device__ int   g_slot[T_TOK];

// ---------------- helpers ----------------
__device__ __forceinline__ uint32_t smem_u32(const void* p) {
    uint32_t a;
    asm("{ .reg .u64 t; cvta.to.shared.u64 t, %1; cvt.u32.u64 %0, t; }" : "=r"(a) : "l"(p));
    return a;
}
__device__ __forceinline__ float tf32r(float v) {
    uint32_t u;
    asm("cvt.rna.tf32.f32 %0, %1;" : "=r"(u) : "f"(v));
    return __uint_as_float(u);
}

#define CPASYNC16(dst, src) \
    asm volatile("cp.async.cg.shared.global [%0], [%1], 16;" :: "r"(dst), "l"(src) : "memory")
#define CPCOMMIT()  asm volatile("cp.async.commit_group;" ::: "memory")
#define CPWAIT(n)   asm volatile("cp.async.wait_group %0;" :: "n"(n) : "memory")

__device__ __forceinline__ void mma_tf32(float* d, const uint32_t* a, uint32_t b0, uint32_t b1) {
    asm volatile(
        "mma.sync.aligned.m16n8k8.row.col.f32.tf32.tf32.f32 "
        "{%0,%1,%2,%3}, {%4,%5,%6,%7}, {%8,%9}, {%0,%1,%2,%3};"
        : "+f"(d[0]), "+f"(d[1]), "+f"(d[2]), "+f"(d[3])
        : "r"(a[0]), "r"(a[1]), "r"(a[2]), "r"(a[3]), "r"(b0), "r"(b1));
}

__device__ __forceinline__ void ldsm_x4(uint32_t* r, uint32_t addr) {
    asm volatile("ldmatrix.sync.aligned.m8n8.x4.shared.b16 {%0,%1,%2,%3}, [%4];"
        : "=r"(r[0]), "=r"(r[1]), "=r"(r[2]), "=r"(r[3]) : "r"(addr));
}

// ---------------- K1: gating ----------------
__global__ void gate_kernel(const float* __restrict__ x, const float* __restrict__ wg)
{
    int warp = (blockIdx.x * blockDim.x + threadIdx.x) >> 5;
    int lane = threadIdx.x & 31;
    if (warp >= T_TOK) return;

    const float* xr = x + (size_t)warp * MDIM;
    float acc[8] = {0.f,0.f,0.f,0.f,0.f,0.f,0.f,0.f};

    #pragma unroll 4
    for (int i = 0; i < MDIM / 32; i++) {
        int m = i * 32 + lane;
        float xv = __ldg(xr + m);
        const float4* w4 = reinterpret_cast<const float4*>(wg + (size_t)m * NEXP);
        float4 a = w4[0], b = w4[1];
        acc[0] += xv * a.x; acc[1] += xv * a.y;
        acc[2] += xv * a.z; acc[3] += xv * a.w;
        acc[4] += xv * b.x; acc[5] += xv * b.y;
        acc[6] += xv * b.z; acc[7] += xv * b.w;
    }
    #pragma unroll
    for (int e = 0; e < 8; e++)
        #pragma unroll
        for (int off = 16; off > 0; off >>= 1)
            acc[e] += __shfl_xor_sync(0xffffffffu, acc[e], off);

    if (lane == 0) {
        float mx = acc[0]; int bi = 0;
        #pragma unroll
        for (int e = 1; e < 8; e++)
            if (acc[e] > mx) { mx = acc[e]; bi = e; }
        float s = 0.f;
        #pragma unroll
        for (int e = 0; e < 8; e++) s += expf(acc[e] - mx);
        g_expert[warp] = bi;
        g_gate[warp]   = 1.0f / s;
    }
}

// ---------------- K2: ordered per-expert rank (two-level shuffle scan) ----------------
__global__ void pos_kernel()
{
    __shared__ int wtot[32][8];
    const int tid = threadIdx.x;
    const int lane = tid & 31, wp = tid >> 5;
    const int base_t = tid * 8;

    int cnt[8] = {0,0,0,0,0,0,0,0};
    int loc[8];
    #pragma unroll
    for (int i = 0; i < 8; i++) {
        int e = g_expert[base_t + i];
        loc[i] = e;
        cnt[e]++;
    }

    int inc[8];
    #pragma unroll
    for (int e = 0; e < 8; e++) inc[e] = cnt[e];
    #pragma unroll
    for (int off = 1; off < 32; off <<= 1) {
        #pragma unroll
        for (int e = 0; e < 8; e++) {
            int v = __shfl_up_sync(0xffffffffu, inc[e], off);
            if (lane >= off) inc[e] += v;
        }
    }
    if (lane == 31) {
        #pragma unroll
        for (int e = 0; e < 8; e++) wtot[wp][e] = inc[e];
    }
    __syncthreads();

    if (wp == 0) {
        int t[8];
        #pragma unroll
        for (int e = 0; e < 8; e++) t[e] = wtot[lane][e];
        #pragma unroll
        for (int off = 1; off < 32; off <<= 1) {
            #pragma unroll
            for (int e = 0; e < 8; e++) {
                int v = __shfl_up_sync(0xffffffffu, t[e], off);
                if (lane >= off) t[e] += v;
            }
        }
        #pragma unroll
        for (int e = 0; e < 8; e++) wtot[lane][e] = t[e];
    }
    __syncthreads();

    int run[8];
    #pragma unroll
    for (int e = 0; e < 8; e++)
        run[e] = (wp > 0 ? wtot[wp - 1][e] : 0) + inc[e] - cnt[e];

    #pragma unroll
    for (int i = 0; i < 8; i++) {
        int e = loc[i];
        int p = run[e]++;
        g_slot[base_t + i] = (p < CAP) ? (e * CAP + p) : -1;
    }
}

// ---------------- K3: scatter (+ tf32 rounding) ----------------
__global__ void scatter_kernel(const float* __restrict__ x)
{
    int t = blockIdx.x;
    int s = g_slot[t];
    if (s < 0) return;
    float4 v = reinterpret_cast<const float4*>(x + (size_t)t * MDIM)[threadIdx.x];
    v.x = tf32r(v.x); v.y = tf32r(v.y); v.z = tf32r(v.z); v.w = tf32r(v.w);
    reinterpret_cast<float4*>(g_disp + (size_t)s * MDIM)[threadIdx.x] = v;
}

// ---------------- K4: tf32 mma.sync GEMM (R15 body + K-split) ----------------
// 512 threads, 16 warps (4x4), warp tile 32x32, CTA tile 128x128, BK=32.
// 3-stage cp.async, one syncthreads/iter. A via ldmatrix.x4; B scalar LDS.32
// raw f32 (HW tf32 truncation). smem As [128][36], Bs [32][136].
// NSPLIT: blockIdx.z = expert + split*NEXP; split sp covers K rows
// [sp*Klen, (sp+1)*Klen), writes Cg0 (sp=0, real bias) or Cg1 (sp=1, zero bias).
#define A_ST 4608   // 128*36 floats per stage
#define B_ST 4352   // 32*136 floats per stage
#define NSTAGE 3
#define GEMM_SMEM (NSTAGE * (A_ST + B_ST) * 4)   // 107520 bytes

template<bool RELU, bool CVT>
__global__ void __launch_bounds__(512, 2)
moe_gemm(const float* __restrict__ Ag, const float* __restrict__ Bg,
         const float* __restrict__ biasg, const float* __restrict__ zbias,
         float* __restrict__ Cg0, float* __restrict__ Cg1,
         int Ndim, int Kstride, int Klen)
{
    extern __shared__ float sm[];
    const uint32_t su = smem_u32(sm);
    const int tid = threadIdx.x;
    const int wid = tid >> 5, lane = tid & 31;
    const int g = lane >> 2, tg = lane & 3;
    const int wm = (wid >> 2) * 32;          // warp row base: 0/32/64/96
    const int wn = (wid & 3) * 32;           // warp col base: 0/32/64/96

    const int lrow = (lane & 7) + ((lane >> 3) & 1) * 8;   // 0..15
    const int lcol = (lane >> 4) * 4;                      // 0 or 4

    const int zz = blockIdx.z;
    const int e  = zz & (NEXP - 1);
    const int sp = zz >> 3;                  // 0 or 1
    const float* A = Ag + (size_t)e * CAP * Kstride
                        + (size_t)(blockIdx.y * 128) * Kstride + (size_t)sp * Klen;
    const float* B = Bg + (size_t)e * Kstride * Ndim
                        + (size_t)sp * Klen * Ndim + blockIdx.x * 128;
    const float* bias = (sp == 0 ? biasg + (size_t)e * Ndim : zbias) + blockIdx.x * 128;
    float* C = (sp == 0 ? Cg0 : Cg1) + (size_t)e * CAP * Ndim
               + (size_t)(blockIdx.y * 128) * Ndim + blockIdx.x * 128;

    const int arow = tid >> 2, acol = (tid & 3) * 8;    // A: 4 thr/row, 2x16B each
    const int brow = tid >> 4, bcol = (tid & 15) * 4;   // B: 16 thr/row, 2x16B

    float acc[2][4][4];
    #pragma unroll
    for (int i = 0; i < 2; i++)
        #pragma unroll
        for (int j = 0; j < 4; j++)
            #pragma unroll
            for (int q = 0; q < 4; q++) acc[i][j][q] = 0.f;

    auto load_stage = [&](int kt, int s) {
        const float* ag = A + (size_t)arow * Kstride + kt * 32 + acol;
        uint32_t ad = su + (uint32_t)(s * (A_ST + B_ST) + arow * 36 + acol) * 4;
        CPASYNC16(ad,      ag);
        CPASYNC16(ad + 16, ag + 4);
        const float* bg = B + (size_t)(kt * 32 + brow) * Ndim + bcol;
        uint32_t bd = su + (uint32_t)(s * (A_ST + B_ST) + A_ST + brow * 136 + bcol) * 4;
        CPASYNC16(bd,       bg);
        CPASYNC16(bd + 256, bg + 64);   // +64 cols = +256 bytes
        CPCOMMIT();
    };

    const int KT = Klen >> 5;
    load_stage(0, 0);
    load_stage(1, 1);

    int s = 0;          // stage holding kt
    int sw = 2;         // stage to write kt+2 into
    for (int kt = 0; kt < KT; kt++) {
        if (kt + 1 < KT) { CPWAIT(1); } else { CPWAIT(0); }
        __syncthreads();

        const uint32_t asu = su + (uint32_t)(s * (A_ST + B_ST)) * 4;
        const float* bs = sm + s * (A_ST + B_ST) + A_ST;
        const uint32_t abase = asu + (uint32_t)((wm + lrow) * 36 + lcol) * 4;

        #pragma unroll
        for (int ks = 0; ks < 4; ks++) {
            const int k0 = ks * 8;
            uint32_t afr[2][4];
            ldsm_x4(afr[0], abase + (uint32_t)(k0) * 4);
            ldsm_x4(afr[1], abase + (uint32_t)(16 * 36 + k0) * 4);
            #pragma unroll
            for (int j = 0; j < 4; j++) {
                const float* bp = bs + (k0 + tg) * 136 + wn + j * 8 + g;
                uint32_t b0 = __float_as_uint(bp[0]);       // raw f32: HW tf32 truncation
                uint32_t b1 = __float_as_uint(bp[4 * 136]);
                mma_tf32(acc[0][j], afr[0], b0, b1);
                mma_tf32(acc[1][j], afr[1], b0, b1);
            }
        }

        if (kt + 2 < KT) load_stage(kt + 2, sw);
        if (++s == NSTAGE) s = 0;
        if (++sw == NSTAGE) sw = 0;
    }

    // epilogue
    #pragma unroll
    for (int j = 0; j < 4; j++) {
        const int col = wn + j * 8 + 2 * tg;
        float2 bv = *reinterpret_cast<const float2*>(bias + col);
        #pragma unroll
        for (int i = 0; i < 2; i++) {
            const int r0 = wm + i * 16 + g;
            float v00 = acc[i][j][0] + bv.x, v01 = acc[i][j][1] + bv.y;
            float v10 = acc[i][j][2] + bv.x, v11 = acc[i][j][3] + bv.y;
            if (RELU) {
                v00 = fmaxf(v00, 0.f); v01 = fmaxf(v01, 0.f);
                v10 = fmaxf(v10, 0.f); v11 = fmaxf(v11, 0.f);
            }
            if (CVT) {
                v00 = tf32r(v00); v01 = tf32r(v01);
                v10 = tf32r(v10); v11 = tf32r(v11);
            }
            *reinterpret_cast<float2*>(C + (size_t)r0 * Ndim + col) = make_float2(v00, v01);
            *reinterpret_cast<float2*>(C + (size_t)(r0 + 8) * Ndim + col) = make_float2(v10, v11);
        }
    }
}

// ---------------- K6: gather (fused K-split reduction) ----------------
__global__ void gather_kernel(float* __restrict__ out)
{
    int t = blockIdx.x;
    int s = g_slot[t];
    float4* dst = reinterpret_cast<float4*>(out + (size_t)t * MDIM);
    if (s < 0) {
        dst[threadIdx.x] = make_float4(0.f, 0.f, 0.f, 0.f);
        return;
    }
    float g = g_gate[t];
    float4 a = reinterpret_cast<const float4*>(g_oute  + (size_t)s * MDIM)[threadIdx.x];
    float4 b = reinterpret_cast<const float4*>(g_oute2 + (size_t)s * MDIM)[threadIdx.x];
    dst[threadIdx.x] = make_float4((a.x + b.x) * g, (a.y + b.y) * g,
                                   (a.z + b.z) * g, (a.w + b.w) * g);
}

// ---------------- launch ----------------
extern "C" void kernel_launch(void* const* d_in, const int* in_sizes, int n_in,
                              void* d_out, int out_size)
{
    const float* x  = (const float*)d_in[0];
    const float* wg = (const float*)d_in[1];
    const float* w1 = (const float*)d_in[2];
    const float* b1 = (const float*)d_in[3];
    const float* w2 = (const float*)d_in[4];
    const float* b2 = (const float*)d_in[5];
    float* out = (float*)d_out;

    float *disp, *h, *oute, *oute2, *zb;
    cudaGetSymbolAddress((void**)&disp,  g_disp);
    cudaGetSymbolAddress((void**)&h,     g_h);
    cudaGetSymbolAddress((void**)&oute,  g_oute);
    cudaGetSymbolAddress((void**)&oute2, g_oute2);
    cudaGetSymbolAddress((void**)&zb,    g_zbias);

    cudaFuncSetAttribute(moe_gemm<true, true>,
                         cudaFuncAttributeMaxDynamicSharedMemorySize, GEMM_SMEM);
    cudaFuncSetAttribute(moe_gemm<false, false>,
                         cudaFuncAttributeMaxDynamicSharedMemorySize, GEMM_SMEM);

    gate_kernel<<<T_TOK / 8, 256>>>(x, wg);
    pos_kernel<<<1, 1024>>>();
    scatter_kernel<<<T_TOK, 256>>>(x);

    // GEMM1: h = relu(disp @ w1 + b1), no split (grid z = 8 -> sp = 0)
    moe_gemm<true, true><<<dim3(DFFD / 128, CAP / 128, NEXP), 512, GEMM_SMEM>>>(
        disp, w1, b1, zb, h, h, DFFD, MDIM, MDIM);

    // GEMM2: oute/oute2 = h @ w2 (+ b2 in split 0), K split in 2, ONE launch
    moe_gemm<false, false><<<dim3(MDIM / 128, CAP / 128, NEXP * 2), 512, GEMM_SMEM>>>(
        h, w2, b2, zb, oute, oute2, MDIM, DFFD, DFFD / 2);

    gather_kernel<<<T_TOK, 256>>>(out);
}